// round 16
// baseline (speedup 1.0000x reference)
#include <cuda_runtime.h>
#include <cuda_fp16.h>
#include <cstdint>

#define F_IN  10
#define HID   32
#define OUTF  2
#define TMW   32           // nodes per warp-tile (two 16-row MMA halves)
#define WPC   8
#define BLK   256

#define XSH   56           // fp16 A-buffer row stride (112B; 8-row groups conflict-free)

// column layout (K=48 = 3 fp16 k-steps):
//   XH1: x 0..9 | zero 10..15 | h  16..47
//   XH2:        (unused)      | rh 16..47   (GEMM2 kt=0 reads XH1 cols 0..15)

// per-warp floats: XH1 fp16 32x56 (=896 f), XH2 fp16 32x56 (=896 f)
#define WARP_F 1792

// smem float offsets
#define SM_BZR   0                          // 384 uint4  = 1536 floats
#define SM_BH    1536                       // 192 uint4  =  768 floats
#define SM_BIAS  2304                       // 96 (bz AND br entries stored PRE-HALVED)
#define SM_WLIN  2400                       // 64
#define SM_BLIN  2464                       // 2 (pad to 2472)
#define SM_DATA  2472
#define SM_TOT_F (SM_DATA + WPC * WARP_F)   // 16808 floats = 67232 B

// ---------------- device helpers -------------------------------------------
__device__ __forceinline__ uint32_t pack_h2(float a, float b) {
    __half2 h = __floats2half2_rn(a, b);
    return *(uint32_t*)&h;
}
__device__ __forceinline__ float2 unpack_h2(uint32_t u) {
    __half2 h = *(__half2*)&u;
    return __half22float2(h);
}
__device__ __forceinline__ uint32_t smem_u32p(const void* p) {
    uint32_t a;
    asm("{ .reg .u64 t; cvta.to.shared.u64 t, %1; cvt.u32.u64 %0, t; }" : "=r"(a) : "l"(p));
    return a;
}
__device__ __forceinline__ void ldm_x4(uint32_t& r0, uint32_t& r1, uint32_t& r2, uint32_t& r3,
                                       uint32_t addr) {
    asm volatile("ldmatrix.sync.aligned.m8n8.x4.shared.b16 {%0,%1,%2,%3}, [%4];"
                 : "=r"(r0), "=r"(r1), "=r"(r2), "=r"(r3) : "r"(addr));
}
__device__ __forceinline__ void mma_f16(float d[4],
                                        uint32_t a0, uint32_t a1, uint32_t a2, uint32_t a3,
                                        uint32_t b0, uint32_t b1) {
    asm volatile(
        "mma.sync.aligned.m16n8k16.row.col.f32.f16.f16.f32 "
        "{%0,%1,%2,%3}, {%4,%5,%6,%7}, {%8,%9}, {%0,%1,%2,%3};"
        : "+f"(d[0]), "+f"(d[1]), "+f"(d[2]), "+f"(d[3])
        : "r"(a0), "r"(a1), "r"(a2), "r"(a3), "r"(b0), "r"(b1));
}
__device__ __forceinline__ float tanh_apx(float v) {
    float r; asm("tanh.approx.f32 %0, %1;" : "=f"(r) : "f"(v));
    return r;
}
// packed sigmoid: in = packed(0.5*pre); out = 0.5*tanh(in)+0.5 (two fp16 lanes)
__device__ __forceinline__ uint32_t sig_h2(uint32_t pre_half) {
    const uint32_t HALF2 = 0x38003800u;   // {0.5h, 0.5h}
    uint32_t th, sg;
    asm volatile("tanh.approx.f16x2 %0, %1;" : "=r"(th) : "r"(pre_half));
    asm volatile("fma.rn.f16x2 %0, %1, %2, %2;" : "=r"(sg) : "r"(th), "r"(HALF2));
    return sg;
}
// packed sigmoid*h: in = packed(0.5*pre), h2 raw; out = sig(pre)*h2
__device__ __forceinline__ uint32_t sigh_h2(uint32_t pre_half, uint32_t h2) {
    uint32_t sg = sig_h2(pre_half), rh;
    asm volatile("mul.rn.f16x2 %0, %1, %2;" : "=r"(rh) : "r"(sg), "r"(h2));
    return rh;
}
// physical k (0..47) -> weight row: k<10 -> k ; 16<=k<48 -> k-6 ; else zero row
__device__ __forceinline__ int kmap(int kb) {
    return (kb < 10) ? kb : ((kb >= 16 && kb < 48) ? kb - 6 : -1);
}

// ---------------- single fused persistent kernel ----------------------------
__global__ void __launch_bounds__(BLK, 2) dcrnn_mma(
    const float* __restrict__ x, const float* __restrict__ h,
    float* __restrict__ out, float* __restrict__ hnew,
    const float* __restrict__ Wz, const float* __restrict__ bz,
    const float* __restrict__ Wr, const float* __restrict__ br,
    const float* __restrict__ Wh, const float* __restrict__ bh,
    const float* __restrict__ Wlin, const float* __restrict__ blin,
    int n, int ntiles)
{
    extern __shared__ float sm[];
    const int t = threadIdx.x;

    // ---- in-CTA weight prep: fold W[0]+W[1], fp16 B frags, nt-PAIR uint4 ----
    {
        uint4* dBZR = (uint4*)(sm + SM_BZR);
        for (int idx = t; idx < 384; idx += BLK) {          // 3kt * 4q * 32 lanes
            int lane = idx & 31, q = (idx >> 5) & 3, kt = idx / 128;
            int c = lane & 3, gg = lane >> 2;
            int kb = kt * 16 + 2 * c;
            int km[4] = { kmap(kb), kmap(kb + 1), kmap(kb + 8), kmap(kb + 9) };
            uint32_t r[4];
            #pragma unroll
            for (int u = 0; u < 2; u++) {
                int np = (2 * q + u) * 8 + gg;              // z:0..31 | r:32..63
                const float* W = (np < 32) ? Wz : Wr;
                int j = np & 31;
                float v[4];
                #pragma unroll
                for (int m = 0; m < 4; m++)
                    v[m] = (km[m] >= 0) ? W[km[m] * 32 + j] + W[1344 + km[m] * 32 + j] : 0.0f;
                r[2 * u]     = pack_h2(v[0], v[1]);
                r[2 * u + 1] = pack_h2(v[2], v[3]);
            }
            dBZR[idx] = make_uint4(r[0], r[1], r[2], r[3]);
        }
        uint4* dBH = (uint4*)(sm + SM_BH);
        for (int idx = t; idx < 192; idx += BLK) {          // 3kt * 2q * 32 lanes
            int lane = idx & 31, q = (idx >> 5) & 1, kt = idx / 64;
            int c = lane & 3, gg = lane >> 2;
            int kb = kt * 16 + 2 * c;
            int km[4] = { kmap(kb), kmap(kb + 1), kmap(kb + 8), kmap(kb + 9) };
            uint32_t r[4];
            #pragma unroll
            for (int u = 0; u < 2; u++) {
                int j = (2 * q + u) * 8 + gg;
                float v[4];
                #pragma unroll
                for (int m = 0; m < 4; m++)
                    v[m] = (km[m] >= 0) ? Wh[km[m] * 32 + j] + Wh[1344 + km[m] * 32 + j] : 0.0f;
                r[2 * u]     = pack_h2(v[0], v[1]);
                r[2 * u + 1] = pack_h2(v[2], v[3]);
            }
            dBH[idx] = make_uint4(r[0], r[1], r[2], r[3]);
        }
        // NOTE: bz AND br entries stored pre-halved (gates use 0.5*(acc+b) before tanh)
        if (t < 96) sm[SM_BIAS + t] = (t < 32) ? 0.5f * bz[t]
                                    : ((t < 64) ? 0.5f * br[t - 32] : bh[t - 64]);
        if (t < 64) sm[SM_WLIN + t] = Wlin[t];
        if (t < 2)  sm[SM_BLIN + t] = blin[t];
    }

    const int warp = t >> 5, lane = t & 31;
    float* wbase = sm + SM_DATA + warp * WARP_F;
    __half* XH1 = (__half*)(wbase);          // x | pad | h
    __half* XH2 = (__half*)(wbase + 896);    //          rh
    const uint32_t uXH1 = smem_u32p(XH1);
    const uint32_t uXH2 = smem_u32p(XH2);

    // static zero pads: XH1 cols 10..15 only
    {
        int r = lane;
        *(uint32_t*)&XH1[r * XSH + 10] = 0;
        *(uint32_t*)&XH1[r * XSH + 12] = 0;
        *(uint32_t*)&XH1[r * XSH + 14] = 0;
    }
    __syncthreads();

    const uint4*  sBZR4 = (const uint4*)(sm + SM_BZR);
    const uint4*  sBH4  = (const uint4*)(sm + SM_BH);
    const float*  sBias = sm + SM_BIAS;
    const float*  sWlin = sm + SM_WLIN;
    const float   blin0 = sm[SM_BLIN], blin1 = sm[SM_BLIN + 1];

    const int g = lane >> 2, c = lane & 3;
    // ldmatrix base addresses: lane -> row (lane&15), col-halfword ((lane>>4)*8)
    const uint32_t lmoff = (uint32_t)(lane & 15) * (XSH * 2) + (uint32_t)(lane >> 4) * 16;
    const uint32_t lm1h0 = uXH1 + lmoff;                    // XH1 rows 0-15
    const uint32_t lm1h1 = lm1h0 + 16 * (XSH * 2);          // XH1 rows 16-31
    const uint32_t lm2h0 = uXH2 + lmoff;
    const uint32_t lm2h1 = lm2h0 + 16 * (XSH * 2);

    const int gwarp = blockIdx.x * WPC + warp;
    const int nwarps = gridDim.x * WPC;

    for (int tile = gwarp; tile < ntiles; tile += nwarps) {
        const int node0 = tile * TMW;
        const int nvalid = min(n - node0, TMW);
        __syncwarp();   // prior-tile smem reads done before restage

        // ---- stage h (fp16, cols 16..47) and x (fp16, cols 0..9) ----
        {
            const float4* gh = (const float4*)(h + (size_t)node0 * HID);
            #pragma unroll
            for (int i = 0; i < 8; i++) {
                int e = i * 32 + lane;
                int nd = e >> 3, cc = e & 7;
                if (nd < nvalid) {
                    float4 v = gh[e];
                    uint2 p = make_uint2(pack_h2(v.x, v.y), pack_h2(v.z, v.w));
                    *(uint2*)&XH1[nd * XSH + 16 + 4 * cc] = p;
                }
            }
            if (lane < nvalid) {
                const float2* gx = (const float2*)(x + (size_t)(node0 + lane) * F_IN);
                #pragma unroll
                for (int i = 0; i < 5; i++) {
                    float2 v = gx[i];
                    *(uint32_t*)&XH1[lane * XSH + 2 * i] = pack_h2(v.x, v.y);
                }
            }
        }
        __syncwarp();

        // ---- GEMM1: z|r preactivations (K=48 in 3 fp16 k-steps, ldmatrix A) ----
        float acc0[8][4], acc1[8][4];
        #pragma unroll
        for (int nt = 0; nt < 8; nt++)
            #pragma unroll
            for (int u = 0; u < 4; u++) { acc0[nt][u] = 0.f; acc1[nt][u] = 0.f; }

        #pragma unroll
        for (int kt = 0; kt < 3; kt++) {
            uint32_t p00, p01, p02, p03, p10, p11, p12, p13;
            ldm_x4(p00, p01, p02, p03, lm1h0 + kt * 32);
            ldm_x4(p10, p11, p12, p13, lm1h1 + kt * 32);
            #pragma unroll
            for (int q = 0; q < 4; q++) {
                uint4 b = sBZR4[(kt * 4 + q) * 32 + lane];
                mma_f16(acc0[2*q],   p00, p01, p02, p03, b.x, b.y);
                mma_f16(acc1[2*q],   p10, p11, p12, p13, b.x, b.y);
                mma_f16(acc0[2*q+1], p00, p01, p02, p03, b.z, b.w);
                mma_f16(acc1[2*q+1], p10, p11, p12, p13, b.z, b.w);
            }
        }

        // ---- epilogue 1: z packed f16x2 in regs; rh via tanh.f16x2 -> XH2 ----
        uint32_t z0p[8], z1p[8];   // [2*nt] rows g / [2*nt+1] rows g+8 (cols j0,j0+1)
        #pragma unroll
        for (int nt = 0; nt < 4; nt++) {
            int j0 = nt * 8 + 2 * c;
            float2 bb = *(const float2*)&sBias[j0];          // pre-halved bz
            z0p[2*nt]   = sig_h2(pack_h2(fmaf(acc0[nt][0], 0.5f, bb.x),
                                         fmaf(acc0[nt][1], 0.5f, bb.y)));
            z0p[2*nt+1] = sig_h2(pack_h2(fmaf(acc0[nt][2], 0.5f, bb.x),
                                         fmaf(acc0[nt][3], 0.5f, bb.y)));
            z1p[2*nt]   = sig_h2(pack_h2(fmaf(acc1[nt][0], 0.5f, bb.x),
                                         fmaf(acc1[nt][1], 0.5f, bb.y)));
            z1p[2*nt+1] = sig_h2(pack_h2(fmaf(acc1[nt][2], 0.5f, bb.x),
                                         fmaf(acc1[nt][3], 0.5f, bb.y)));
        }
        #pragma unroll
        for (int nt = 0; nt < 4; nt++) {             // gate row block nt+4 = r gate
            int j0 = nt * 8 + 2 * c;
            float2 bb = *(const float2*)&sBias[32 + j0];   // pre-halved br
            {
                uint32_t h0 = *(const uint32_t*)&XH1[g * XSH + 16 + j0];
                uint32_t h8 = *(const uint32_t*)&XH1[(g + 8) * XSH + 16 + j0];
                uint32_t pre0 = pack_h2(fmaf(acc0[nt+4][0], 0.5f, bb.x),
                                        fmaf(acc0[nt+4][1], 0.5f, bb.y));
                uint32_t pre8 = pack_h2(fmaf(acc0[nt+4][2], 0.5f, bb.x),
                                        fmaf(acc0[nt+4][3], 0.5f, bb.y));
                *(uint32_t*)&XH2[g * XSH + 16 + j0]       = sigh_h2(pre0, h0);
                *(uint32_t*)&XH2[(g + 8) * XSH + 16 + j0] = sigh_h2(pre8, h8);
            }
            {
                uint32_t h0 = *(const uint32_t*)&XH1[(16 + g) * XSH + 16 + j0];
                uint32_t h8 = *(const uint32_t*)&XH1[(24 + g) * XSH + 16 + j0];
                uint32_t pre0 = pack_h2(fmaf(acc1[nt+4][0], 0.5f, bb.x),
                                        fmaf(acc1[nt+4][1], 0.5f, bb.y));
                uint32_t pre8 = pack_h2(fmaf(acc1[nt+4][2], 0.5f, bb.x),
                                        fmaf(acc1[nt+4][3], 0.5f, bb.y));
                *(uint32_t*)&XH2[(16 + g) * XSH + 16 + j0] = sigh_h2(pre0, h0);
                *(uint32_t*)&XH2[(24 + g) * XSH + 16 + j0] = sigh_h2(pre8, h8);
            }
        }
        __syncwarp();

        // ---- GEMM2: candidate (kt=0 -> XH1 x|pad, kt>=1 -> XH2 rh) ----
        float acc20[4][4], acc21[4][4];
        #pragma unroll
        for (int nt = 0; nt < 4; nt++)
            #pragma unroll
            for (int u = 0; u < 4; u++) { acc20[nt][u] = 0.f; acc21[nt][u] = 0.f; }

        #pragma unroll
        for (int kt = 0; kt < 3; kt++) {
            uint32_t a0 = (kt == 0) ? lm1h0 : (lm2h0 + kt * 32);
            uint32_t a1 = (kt == 0) ? lm1h1 : (lm2h1 + kt * 32);
            uint32_t p00, p01, p02, p03, p10, p11, p12, p13;
            ldm_x4(p00, p01, p02, p03, a0);
            ldm_x4(p10, p11, p12, p13, a1);
            #pragma unroll
            for (int q = 0; q < 2; q++) {
                uint4 b = sBH4[(kt * 2 + q) * 32 + lane];
                mma_f16(acc20[2*q],   p00, p01, p02, p03, b.x, b.y);
                mma_f16(acc21[2*q],   p10, p11, p12, p13, b.x, b.y);
                mma_f16(acc20[2*q+1], p00, p01, p02, p03, b.z, b.w);
                mma_f16(acc21[2*q+1], p10, p11, p12, p13, b.z, b.w);
            }
        }

        // ---- epilogue 2: blend + head + direct stores ----
        #pragma unroll
        for (int half = 0; half < 2; half++) {
            int rA = half * 16 + g, rB = rA + 8;
            const bool okA = rA < nvalid, okB = rB < nvalid;
            float po00 = 0.f, po01 = 0.f, po80 = 0.f, po81 = 0.f;
            #pragma unroll
            for (int nt = 0; nt < 4; nt++) {
                float a0 = half ? acc21[nt][0] : acc20[nt][0];
                float a1 = half ? acc21[nt][1] : acc20[nt][1];
                float a2 = half ? acc21[nt][2] : acc20[nt][2];
                float a3 = half ? acc21[nt][3] : acc20[nt][3];
                float2 zzA = unpack_h2(half ? z1p[2*nt]   : z0p[2*nt]);
                float2 zzB = unpack_h2(half ? z1p[2*nt+1] : z0p[2*nt+1]);
                int j0 = nt * 8 + 2 * c;
                float2 bb = *(const float2*)&sBias[64 + j0];
                float2 h0 = unpack_h2(*(const uint32_t*)&XH1[rA * XSH + 16 + j0]);
                float2 h8 = unpack_h2(*(const uint32_t*)&XH1[rB * XSH + 16 + j0]);
                float ht, hn00, hn01, hn80, hn81;
                ht = tanh_apx(a0 + bb.x); hn00 = ht + zzA.x * (h0.x - ht);
                ht = tanh_apx(a1 + bb.y); hn01 = ht + zzA.y * (h0.y - ht);
                ht = tanh_apx(a2 + bb.x); hn80 = ht + zzB.x * (h8.x - ht);
                ht = tanh_apx(a3 + bb.y); hn81 = ht + zzB.y * (h8.y - ht);

                float2 wA = *(const float2*)&sWlin[j0];
                float2 wB = *(const float2*)&sWlin[32 + j0];
                float r;
                r = fmaxf(hn00, 0.f); po00 = fmaf(r, wA.x, po00); po01 = fmaf(r, wB.x, po01);
                r = fmaxf(hn01, 0.f); po00 = fmaf(r, wA.y, po00); po01 = fmaf(r, wB.y, po01);
                r = fmaxf(hn80, 0.f); po80 = fmaf(r, wA.x, po80); po81 = fmaf(r, wB.x, po81);
                r = fmaxf(hn81, 0.f); po80 = fmaf(r, wA.y, po80); po81 = fmaf(r, wB.y, po81);

                if (okA) *(float2*)&hnew[(size_t)(node0 + rA) * HID + j0] = make_float2(hn00, hn01);
                if (okB) *(float2*)&hnew[(size_t)(node0 + rB) * HID + j0] = make_float2(hn80, hn81);
            }
            #pragma unroll
            for (int s = 1; s <= 2; s <<= 1) {
                po00 += __shfl_xor_sync(0xFFFFFFFFu, po00, s);
                po01 += __shfl_xor_sync(0xFFFFFFFFu, po01, s);
                po80 += __shfl_xor_sync(0xFFFFFFFFu, po80, s);
                po81 += __shfl_xor_sync(0xFFFFFFFFu, po81, s);
            }
            if (c == 0) {
                if (okA) *(float2*)&out[(size_t)(node0 + rA) * OUTF] = make_float2(po00 + blin0, po01 + blin1);
                if (okB) *(float2*)&out[(size_t)(node0 + rB) * OUTF] = make_float2(po80 + blin0, po81 + blin1);
            }
        }
    }
}

// ---------------------------------------------------------------------------
extern "C" void kernel_launch(void* const* d_in, const int* in_sizes, int n_in,
                              void* d_out, int out_size)
{
    const float* x    = (const float*)d_in[0];
    // d_in[1] edge_index, d_in[2] edge_weight: mathematically unused (K=1)
    const float* h    = (const float*)d_in[3];
    const float* Wz   = (const float*)d_in[4];
    const float* bz   = (const float*)d_in[5];
    const float* Wr   = (const float*)d_in[6];
    const float* br   = (const float*)d_in[7];
    const float* Wh   = (const float*)d_in[8];
    const float* bh   = (const float*)d_in[9];
    const float* Wlin = (const float*)d_in[10];
    const float* blin = (const float*)d_in[11];

    int n = in_sizes[0] / F_IN;
    float* out  = (float*)d_out;             // [n, 2]
    float* hnew = out + (size_t)n * OUTF;    // [n, 32]

    int ntiles = (n + TMW - 1) / TMW;
    int ctas = (ntiles + WPC - 1) / WPC;
    if (ctas > 296) ctas = 296;              // 2 persistent CTAs per SM

    cudaFuncSetAttribute(dcrnn_mma, cudaFuncAttributeMaxDynamicSharedMemorySize,
                         SM_TOT_F * 4);

    dcrnn_mma<<<ctas, BLK, SM_TOT_F * 4>>>(x, h, out, hnew,
                                           Wz, bz, Wr, br, Wh, bh, Wlin, blin,
                                           n, ntiles);
}

// round 17
// speedup vs baseline: 1.0342x; 1.0342x over previous
#include <cuda_runtime.h>
#include <cuda_fp16.h>
#include <cstdint>

#define F_IN  10
#define HID   32
#define OUTF  2
#define TMW   32           // nodes per warp-tile (two 16-row MMA halves)
#define WPC   8
#define BLK   256

#define XSH   56           // fp16 A-buffer row stride (112B; 8-row groups conflict-free)

// column layout (K=48 = 3 fp16 k-steps):
//   XH1: x 0..9 | zero 10..15 | h  16..47
//   XH2:        (unused)      | rh 16..47   (GEMM2 kt=0 reads XH1 cols 0..15)

// per-warp floats: XH1 fp16 32x56 (=896 f), XH2 fp16 32x56 (=896 f)
#define WARP_F 1792

// smem float offsets
#define SM_BZR   0                          // 384 uint4  = 1536 floats (gate weights PRE-HALVED)
#define SM_BH    1536                       // 192 uint4  =  768 floats
#define SM_BIAS  2304                       // 96 (bz AND br entries stored PRE-HALVED)
#define SM_WLIN  2400                       // 64
#define SM_BLIN  2464                       // 2 (pad to 2472)
#define SM_DATA  2472
#define SM_TOT_F (SM_DATA + WPC * WARP_F)   // 16808 floats = 67232 B

// ---------------- device helpers -------------------------------------------
__device__ __forceinline__ uint32_t pack_h2(float a, float b) {
    __half2 h = __floats2half2_rn(a, b);
    return *(uint32_t*)&h;
}
__device__ __forceinline__ float2 unpack_h2(uint32_t u) {
    __half2 h = *(__half2*)&u;
    return __half22float2(h);
}
__device__ __forceinline__ uint32_t smem_u32p(const void* p) {
    uint32_t a;
    asm("{ .reg .u64 t; cvta.to.shared.u64 t, %1; cvt.u32.u64 %0, t; }" : "=r"(a) : "l"(p));
    return a;
}
__device__ __forceinline__ void ldm_x4(uint32_t& r0, uint32_t& r1, uint32_t& r2, uint32_t& r3,
                                       uint32_t addr) {
    asm volatile("ldmatrix.sync.aligned.m8n8.x4.shared.b16 {%0,%1,%2,%3}, [%4];"
                 : "=r"(r0), "=r"(r1), "=r"(r2), "=r"(r3) : "r"(addr));
}
__device__ __forceinline__ void mma_f16(float d[4],
                                        uint32_t a0, uint32_t a1, uint32_t a2, uint32_t a3,
                                        uint32_t b0, uint32_t b1) {
    asm volatile(
        "mma.sync.aligned.m16n8k16.row.col.f32.f16.f16.f32 "
        "{%0,%1,%2,%3}, {%4,%5,%6,%7}, {%8,%9}, {%0,%1,%2,%3};"
        : "+f"(d[0]), "+f"(d[1]), "+f"(d[2]), "+f"(d[3])
        : "r"(a0), "r"(a1), "r"(a2), "r"(a3), "r"(b0), "r"(b1));
}
__device__ __forceinline__ float tanh_apx(float v) {
    float r; asm("tanh.approx.f32 %0, %1;" : "=f"(r) : "f"(v));
    return r;
}
// sigmoid from pre-halved argument: sig2h(0.5*v) = 0.5*tanh(0.5*v)+0.5 = sigmoid(v)
__device__ __forceinline__ float sig_from_half(float vh) {
    return fmaf(0.5f, tanh_apx(vh), 0.5f);
}
// half2 sigmoid*h: in = packed(0.5*pre), h2 raw; out = (0.5*tanh(in)+0.5)*h2
__device__ __forceinline__ uint32_t sigh_h2(uint32_t pre_half, uint32_t h2) {
    const uint32_t HALF2 = 0x38003800u;   // {0.5h, 0.5h}
    uint32_t th, sg, rh;
    asm volatile("tanh.approx.f16x2 %0, %1;" : "=r"(th) : "r"(pre_half));
    asm volatile("fma.rn.f16x2 %0, %1, %2, %2;" : "=r"(sg) : "r"(th), "r"(HALF2));
    asm volatile("mul.rn.f16x2 %0, %1, %2;" : "=r"(rh) : "r"(sg), "r"(h2));
    return rh;
}
// physical k (0..47) -> weight row: k<10 -> k ; 16<=k<48 -> k-6 ; else zero row
__device__ __forceinline__ int kmap(int kb) {
    return (kb < 10) ? kb : ((kb >= 16 && kb < 48) ? kb - 6 : -1);
}

// ---------------- single fused persistent kernel ----------------------------
__global__ void __launch_bounds__(BLK, 2) dcrnn_mma(
    const float* __restrict__ x, const float* __restrict__ h,
    float* __restrict__ out, float* __restrict__ hnew,
    const float* __restrict__ Wz, const float* __restrict__ bz,
    const float* __restrict__ Wr, const float* __restrict__ br,
    const float* __restrict__ Wh, const float* __restrict__ bh,
    const float* __restrict__ Wlin, const float* __restrict__ blin,
    int n, int ntiles)
{
    extern __shared__ float sm[];
    const int t = threadIdx.x;

    // ---- in-CTA weight prep: fold W[0]+W[1], PRE-HALVE gate weights, fp16 frags ----
    {
        uint4* dBZR = (uint4*)(sm + SM_BZR);
        for (int idx = t; idx < 384; idx += BLK) {          // 3kt * 4q * 32 lanes
            int lane = idx & 31, q = (idx >> 5) & 3, kt = idx / 128;
            int c = lane & 3, gg = lane >> 2;
            int kb = kt * 16 + 2 * c;
            int km[4] = { kmap(kb), kmap(kb + 1), kmap(kb + 8), kmap(kb + 9) };
            uint32_t r[4];
            #pragma unroll
            for (int u = 0; u < 2; u++) {
                int np = (2 * q + u) * 8 + gg;              // z:0..31 | r:32..63
                const float* W = (np < 32) ? Wz : Wr;
                int j = np & 31;
                float v[4];
                #pragma unroll
                for (int m = 0; m < 4; m++)
                    v[m] = (km[m] >= 0)
                         ? 0.5f * (W[km[m] * 32 + j] + W[1344 + km[m] * 32 + j])
                         : 0.0f;
                r[2 * u]     = pack_h2(v[0], v[1]);
                r[2 * u + 1] = pack_h2(v[2], v[3]);
            }
            dBZR[idx] = make_uint4(r[0], r[1], r[2], r[3]);
        }
        uint4* dBH = (uint4*)(sm + SM_BH);
        for (int idx = t; idx < 192; idx += BLK) {          // 3kt * 2q * 32 lanes
            int lane = idx & 31, q = (idx >> 5) & 1, kt = idx / 64;
            int c = lane & 3, gg = lane >> 2;
            int kb = kt * 16 + 2 * c;
            int km[4] = { kmap(kb), kmap(kb + 1), kmap(kb + 8), kmap(kb + 9) };
            uint32_t r[4];
            #pragma unroll
            for (int u = 0; u < 2; u++) {
                int j = (2 * q + u) * 8 + gg;
                float v[4];
                #pragma unroll
                for (int m = 0; m < 4; m++)
                    v[m] = (km[m] >= 0) ? Wh[km[m] * 32 + j] + Wh[1344 + km[m] * 32 + j] : 0.0f;
                r[2 * u]     = pack_h2(v[0], v[1]);
                r[2 * u + 1] = pack_h2(v[2], v[3]);
            }
            dBH[idx] = make_uint4(r[0], r[1], r[2], r[3]);
        }
        // bz AND br pre-halved (gate preacts arrive pre-halved from scaled weights)
        if (t < 96) sm[SM_BIAS + t] = (t < 32) ? 0.5f * bz[t]
                                    : ((t < 64) ? 0.5f * br[t - 32] : bh[t - 64]);
        if (t < 64) sm[SM_WLIN + t] = Wlin[t];
        if (t < 2)  sm[SM_BLIN + t] = blin[t];
    }

    const int warp = t >> 5, lane = t & 31;
    float* wbase = sm + SM_DATA + warp * WARP_F;
    __half* XH1 = (__half*)(wbase);          // x | pad | h
    __half* XH2 = (__half*)(wbase + 896);    //          rh
    const uint32_t uXH1 = smem_u32p(XH1);
    const uint32_t uXH2 = smem_u32p(XH2);

    // static zero pads: XH1 cols 10..15 only
    {
        int r = lane;
        *(uint32_t*)&XH1[r * XSH + 10] = 0;
        *(uint32_t*)&XH1[r * XSH + 12] = 0;
        *(uint32_t*)&XH1[r * XSH + 14] = 0;
    }
    __syncthreads();

    const uint4*  sBZR4 = (const uint4*)(sm + SM_BZR);
    const uint4*  sBH4  = (const uint4*)(sm + SM_BH);
    const float*  sBias = sm + SM_BIAS;
    const float*  sWlin = sm + SM_WLIN;
    const float   blin0 = sm[SM_BLIN], blin1 = sm[SM_BLIN + 1];

    const int g = lane >> 2, c = lane & 3;
    // ldmatrix base addresses: lane -> row (lane&15), col-halfword ((lane>>4)*8)
    const uint32_t lmoff = (uint32_t)(lane & 15) * (XSH * 2) + (uint32_t)(lane >> 4) * 16;
    const uint32_t lm1h0 = uXH1 + lmoff;                    // XH1 rows 0-15
    const uint32_t lm1h1 = lm1h0 + 16 * (XSH * 2);          // XH1 rows 16-31
    const uint32_t lm2h0 = uXH2 + lmoff;
    const uint32_t lm2h1 = lm2h0 + 16 * (XSH * 2);

    const int gwarp = blockIdx.x * WPC + warp;
    const int nwarps = gridDim.x * WPC;

    for (int tile = gwarp; tile < ntiles; tile += nwarps) {
        const int node0 = tile * TMW;
        const int nvalid = min(n - node0, TMW);
        __syncwarp();   // prior-tile smem reads done before restage

        // ---- stage h (fp16, cols 16..47) and x (fp16, cols 0..9) ----
        {
            const float4* gh = (const float4*)(h + (size_t)node0 * HID);
            #pragma unroll
            for (int i = 0; i < 8; i++) {
                int e = i * 32 + lane;
                int nd = e >> 3, cc = e & 7;
                if (nd < nvalid) {
                    float4 v = gh[e];
                    uint2 p = make_uint2(pack_h2(v.x, v.y), pack_h2(v.z, v.w));
                    *(uint2*)&XH1[nd * XSH + 16 + 4 * cc] = p;
                }
            }
            if (lane < nvalid) {
                const float2* gx = (const float2*)(x + (size_t)(node0 + lane) * F_IN);
                #pragma unroll
                for (int i = 0; i < 5; i++) {
                    float2 v = gx[i];
                    *(uint32_t*)&XH1[lane * XSH + 2 * i] = pack_h2(v.x, v.y);
                }
            }
        }
        __syncwarp();

        // ---- GEMM1: z|r HALF-preactivations (weights pre-halved) ----
        float acc0[8][4], acc1[8][4];
        #pragma unroll
        for (int nt = 0; nt < 8; nt++)
            #pragma unroll
            for (int u = 0; u < 4; u++) { acc0[nt][u] = 0.f; acc1[nt][u] = 0.f; }

        #pragma unroll
        for (int kt = 0; kt < 3; kt++) {
            uint32_t p00, p01, p02, p03, p10, p11, p12, p13;
            ldm_x4(p00, p01, p02, p03, lm1h0 + kt * 32);
            ldm_x4(p10, p11, p12, p13, lm1h1 + kt * 32);
            #pragma unroll
            for (int q = 0; q < 4; q++) {
                uint4 b = sBZR4[(kt * 4 + q) * 32 + lane];
                mma_f16(acc0[2*q],   p00, p01, p02, p03, b.x, b.y);
                mma_f16(acc1[2*q],   p10, p11, p12, p13, b.x, b.y);
                mma_f16(acc0[2*q+1], p00, p01, p02, p03, b.z, b.w);
                mma_f16(acc1[2*q+1], p10, p11, p12, p13, b.z, b.w);
            }
        }

        // ---- epilogue 1: z fp32 in regs (FADD+MUFU+FFMA); rh via tanh.f16x2 ----
        float z0[16], z1[16];
        #pragma unroll
        for (int nt = 0; nt < 4; nt++) {
            int j0 = nt * 8 + 2 * c;
            float2 bb = *(const float2*)&sBias[j0];          // pre-halved bz
            z0[nt*4+0] = sig_from_half(acc0[nt][0] + bb.x);
            z0[nt*4+1] = sig_from_half(acc0[nt][1] + bb.y);
            z0[nt*4+2] = sig_from_half(acc0[nt][2] + bb.x);
            z0[nt*4+3] = sig_from_half(acc0[nt][3] + bb.y);
            z1[nt*4+0] = sig_from_half(acc1[nt][0] + bb.x);
            z1[nt*4+1] = sig_from_half(acc1[nt][1] + bb.y);
            z1[nt*4+2] = sig_from_half(acc1[nt][2] + bb.x);
            z1[nt*4+3] = sig_from_half(acc1[nt][3] + bb.y);
        }
        #pragma unroll
        for (int nt = 0; nt < 4; nt++) {             // gate row block nt+4 = r gate
            int j0 = nt * 8 + 2 * c;
            float2 bb = *(const float2*)&sBias[32 + j0];   // pre-halved br
            {
                uint32_t h0 = *(const uint32_t*)&XH1[g * XSH + 16 + j0];
                uint32_t h8 = *(const uint32_t*)&XH1[(g + 8) * XSH + 16 + j0];
                uint32_t pre0 = pack_h2(acc0[nt+4][0] + bb.x, acc0[nt+4][1] + bb.y);
                uint32_t pre8 = pack_h2(acc0[nt+4][2] + bb.x, acc0[nt+4][3] + bb.y);
                *(uint32_t*)&XH2[g * XSH + 16 + j0]       = sigh_h2(pre0, h0);
                *(uint32_t*)&XH2[(g + 8) * XSH + 16 + j0] = sigh_h2(pre8, h8);
            }
            {
                uint32_t h0 = *(const uint32_t*)&XH1[(16 + g) * XSH + 16 + j0];
                uint32_t h8 = *(const uint32_t*)&XH1[(24 + g) * XSH + 16 + j0];
                uint32_t pre0 = pack_h2(acc1[nt+4][0] + bb.x, acc1[nt+4][1] + bb.y);
                uint32_t pre8 = pack_h2(acc1[nt+4][2] + bb.x, acc1[nt+4][3] + bb.y);
                *(uint32_t*)&XH2[(16 + g) * XSH + 16 + j0] = sigh_h2(pre0, h0);
                *(uint32_t*)&XH2[(24 + g) * XSH + 16 + j0] = sigh_h2(pre8, h8);
            }
        }
        __syncwarp();

        // ---- GEMM2: candidate (kt=0 -> XH1 x|pad, kt>=1 -> XH2 rh) ----
        float acc20[4][4], acc21[4][4];
        #pragma unroll
        for (int nt = 0; nt < 4; nt++)
            #pragma unroll
            for (int u = 0; u < 4; u++) { acc20[nt][u] = 0.f; acc21[nt][u] = 0.f; }

        #pragma unroll
        for (int kt = 0; kt < 3; kt++) {
            uint32_t a0 = (kt == 0) ? lm1h0 : (lm2h0 + kt * 32);
            uint32_t a1 = (kt == 0) ? lm1h1 : (lm2h1 + kt * 32);
            uint32_t p00, p01, p02, p03, p10, p11, p12, p13;
            ldm_x4(p00, p01, p02, p03, a0);
            ldm_x4(p10, p11, p12, p13, a1);
            #pragma unroll
            for (int q = 0; q < 2; q++) {
                uint4 b = sBH4[(kt * 2 + q) * 32 + lane];
                mma_f16(acc20[2*q],   p00, p01, p02, p03, b.x, b.y);
                mma_f16(acc21[2*q],   p10, p11, p12, p13, b.x, b.y);
                mma_f16(acc20[2*q+1], p00, p01, p02, p03, b.z, b.w);
                mma_f16(acc21[2*q+1], p10, p11, p12, p13, b.z, b.w);
            }
        }

        // ---- epilogue 2: blend + head + direct stores ----
        #pragma unroll
        for (int half = 0; half < 2; half++) {
            int rA = half * 16 + g, rB = rA + 8;
            const bool okA = rA < nvalid, okB = rB < nvalid;
            float po00 = 0.f, po01 = 0.f, po80 = 0.f, po81 = 0.f;
            #pragma unroll
            for (int nt = 0; nt < 4; nt++) {
                float a0 = half ? acc21[nt][0] : acc20[nt][0];
                float a1 = half ? acc21[nt][1] : acc20[nt][1];
                float a2 = half ? acc21[nt][2] : acc20[nt][2];
                float a3 = half ? acc21[nt][3] : acc20[nt][3];
                float zz0 = half ? z1[nt*4+0] : z0[nt*4+0];
                float zz1 = half ? z1[nt*4+1] : z0[nt*4+1];
                float zz2 = half ? z1[nt*4+2] : z0[nt*4+2];
                float zz3 = half ? z1[nt*4+3] : z0[nt*4+3];
                int j0 = nt * 8 + 2 * c;
                float2 bb = *(const float2*)&sBias[64 + j0];
                float2 h0 = unpack_h2(*(const uint32_t*)&XH1[rA * XSH + 16 + j0]);
                float2 h8 = unpack_h2(*(const uint32_t*)&XH1[rB * XSH + 16 + j0]);
                float ht, hn00, hn01, hn80, hn81;
                ht = tanh_apx(a0 + bb.x); hn00 = ht + zz0 * (h0.x - ht);
                ht = tanh_apx(a1 + bb.y); hn01 = ht + zz1 * (h0.y - ht);
                ht = tanh_apx(a2 + bb.x); hn80 = ht + zz2 * (h8.x - ht);
                ht = tanh_apx(a3 + bb.y); hn81 = ht + zz3 * (h8.y - ht);

                float2 wA = *(const float2*)&sWlin[j0];
                float2 wB = *(const float2*)&sWlin[32 + j0];
                float r;
                r = fmaxf(hn00, 0.f); po00 = fmaf(r, wA.x, po00); po01 = fmaf(r, wB.x, po01);
                r = fmaxf(hn01, 0.f); po00 = fmaf(r, wA.y, po00); po01 = fmaf(r, wB.y, po01);
                r = fmaxf(hn80, 0.f); po80 = fmaf(r, wA.x, po80); po81 = fmaf(r, wB.x, po81);
                r = fmaxf(hn81, 0.f); po80 = fmaf(r, wA.y, po80); po81 = fmaf(r, wB.y, po81);

                if (okA) *(float2*)&hnew[(size_t)(node0 + rA) * HID + j0] = make_float2(hn00, hn01);
                if (okB) *(float2*)&hnew[(size_t)(node0 + rB) * HID + j0] = make_float2(hn80, hn81);
            }
            #pragma unroll
            for (int s = 1; s <= 2; s <<= 1) {
                po00 += __shfl_xor_sync(0xFFFFFFFFu, po00, s);
                po01 += __shfl_xor_sync(0xFFFFFFFFu, po01, s);
                po80 += __shfl_xor_sync(0xFFFFFFFFu, po80, s);
                po81 += __shfl_xor_sync(0xFFFFFFFFu, po81, s);
            }
            if (c == 0) {
                if (okA) *(float2*)&out[(size_t)(node0 + rA) * OUTF] = make_float2(po00 + blin0, po01 + blin1);
                if (okB) *(float2*)&out[(size_t)(node0 + rB) * OUTF] = make_float2(po80 + blin0, po81 + blin1);
            }
        }
    }
}

// ---------------------------------------------------------------------------
extern "C" void kernel_launch(void* const* d_in, const int* in_sizes, int n_in,
                              void* d_out, int out_size)
{
    const float* x    = (const float*)d_in[0];
    // d_in[1] edge_index, d_in[2] edge_weight: mathematically unused (K=1)
    const float* h    = (const float*)d_in[3];
    const float* Wz   = (const float*)d_in[4];
    const float* bz   = (const float*)d_in[5];
    const float* Wr   = (const float*)d_in[6];
    const float* br   = (const float*)d_in[7];
    const float* Wh   = (const float*)d_in[8];
    const float* bh   = (const float*)d_in[9];
    const float* Wlin = (const float*)d_in[10];
    const float* blin = (const float*)d_in[11];

    int n = in_sizes[0] / F_IN;
    float* out  = (float*)d_out;             // [n, 2]
    float* hnew = out + (size_t)n * OUTF;    // [n, 32]

    int ntiles = (n + TMW - 1) / TMW;
    int ctas = (ntiles + WPC - 1) / WPC;
    if (ctas > 296) ctas = 296;              // 2 persistent CTAs per SM

    cudaFuncSetAttribute(dcrnn_mma, cudaFuncAttributeMaxDynamicSharedMemorySize,
                         SM_TOT_F * 4);

    dcrnn_mma<<<ctas, BLK, SM_TOT_F * 4>>>(x, h, out, hnew,
                                           Wz, bz, Wr, br, Wh, bh, Wlin, blin,
                                           n, ntiles);
}